// round 2
// baseline (speedup 1.0000x reference)
#include <cuda_runtime.h>
#include <cstdint>

#define N_NODES 50000
#define N_EDGES 800000
#define D 128          // D_IN == D_OUT == 128
#define D4 (D / 4)     // 32 float4 per row

// Scratch: h = segment_sum(feature[src] -> dst), 50000 x 128 f32 = 25.6 MB.
__device__ float g_h[N_NODES * D];

// ---------------------------------------------------------------------------
// Kernel 1: zero the accumulator (graph replays re-run the scatter, so h must
// be cleared every launch).
// ---------------------------------------------------------------------------
__global__ void zero_h_kernel() {
    int i = blockIdx.x * blockDim.x + threadIdx.x;
    if (i < N_NODES * D4) {
        reinterpret_cast<float4*>(g_h)[i] = make_float4(0.f, 0.f, 0.f, 0.f);
    }
}

// ---------------------------------------------------------------------------
// Kernel 2: warp-per-edge scatter. Lane l handles float4 chunk l of the row.
// feature is 25.6 MB -> L2-resident after first wave; h likewise. RED.v4
// avoids the atomic return trip and quarters the instruction count vs scalar
// atomicAdd.
// ---------------------------------------------------------------------------
__global__ void scatter_kernel(const float* __restrict__ feature,
                               const int* __restrict__ edge_src,
                               const int* __restrict__ edge_dst) {
    int w = (blockIdx.x * blockDim.x + threadIdx.x) >> 5;
    int lane = threadIdx.x & 31;
    if (w >= N_EDGES) return;
    int s = __ldg(edge_src + w);   // same addr across warp -> L1 broadcast
    int d = __ldg(edge_dst + w);

    const float4* f4 = reinterpret_cast<const float4*>(feature) + (size_t)s * D4 + lane;
    float4 v = __ldg(f4);

    float4* h4 = reinterpret_cast<float4*>(g_h) + (size_t)d * D4 + lane;
    asm volatile("red.global.add.v4.f32 [%0], {%1, %2, %3, %4};"
                 :: "l"(h4), "f"(v.x), "f"(v.y), "f"(v.z), "f"(v.w)
                 : "memory");
}

// ---------------------------------------------------------------------------
// Kernel 3: out = relu(h @ W + b).
// 8 warps/block, each warp computes 4 rows x 128 cols. h rows staged in smem
// for conflict-free broadcast; W (64 KB) read through __ldg, stays L1-hot.
// Inner product uses packed fma.rn.f32x2 (2 fp32 FMA per instruction).
// ---------------------------------------------------------------------------
__global__ void gemm_bias_relu_kernel(const float* __restrict__ W,
                                      const float* __restrict__ b,
                                      float* __restrict__ out) {
    __shared__ float s_h[8][4][D];   // 16 KB

    int warp = threadIdx.x >> 5;
    int lane = threadIdx.x & 31;
    int row0 = (blockIdx.x * 8 + warp) * 4;

    // Stage 4 h rows into shared memory (one LDG.128 per row per lane).
    const float4* h4 = reinterpret_cast<const float4*>(g_h);
    #pragma unroll
    for (int r = 0; r < 4; r++) {
        int row = row0 + r;
        float4 v = make_float4(0.f, 0.f, 0.f, 0.f);
        if (row < N_NODES) v = h4[(size_t)row * D4 + lane];
        reinterpret_cast<float4*>(&s_h[warp][r][0])[lane] = v;
    }
    __syncwarp();

    // Accumulators: 4 rows x 4 cols = 16 fp32, held as 8 packed f32x2 pairs.
    unsigned long long acc[4][2];
    #pragma unroll
    for (int r = 0; r < 4; r++) { acc[r][0] = 0ull; acc[r][1] = 0ull; }

    const float4* W4 = reinterpret_cast<const float4*>(W);
    #pragma unroll 4
    for (int k = 0; k < D; k++) {
        float4 wv = __ldg(W4 + (size_t)k * D4 + lane);   // W[k][lane*4 .. +3]
        unsigned long long w01, w23;
        asm("mov.b64 %0, {%1, %2};" : "=l"(w01) : "f"(wv.x), "f"(wv.y));
        asm("mov.b64 %0, {%1, %2};" : "=l"(w23) : "f"(wv.z), "f"(wv.w));
        #pragma unroll
        for (int r = 0; r < 4; r++) {
            float hv = s_h[warp][r][k];                  // smem broadcast
            unsigned long long hh;
            asm("mov.b64 %0, {%1, %1};" : "=l"(hh) : "f"(hv));
            asm("fma.rn.f32x2 %0, %1, %2, %0;" : "+l"(acc[r][0]) : "l"(hh), "l"(w01));
            asm("fma.rn.f32x2 %0, %1, %2, %0;" : "+l"(acc[r][1]) : "l"(hh), "l"(w23));
        }
    }

    float4 bv = __ldg(reinterpret_cast<const float4*>(b) + lane);
    #pragma unroll
    for (int r = 0; r < 4; r++) {
        int row = row0 + r;
        if (row >= N_NODES) break;
        float a0, a1, a2, a3;
        asm("mov.b64 {%0, %1}, %2;" : "=f"(a0), "=f"(a1) : "l"(acc[r][0]));
        asm("mov.b64 {%0, %1}, %2;" : "=f"(a2), "=f"(a3) : "l"(acc[r][1]));
        float4 o;
        o.x = fmaxf(a0 + bv.x, 0.f);
        o.y = fmaxf(a1 + bv.y, 0.f);
        o.z = fmaxf(a2 + bv.z, 0.f);
        o.w = fmaxf(a3 + bv.w, 0.f);
        reinterpret_cast<float4*>(out)[(size_t)row * D4 + lane] = o;
    }
}

// ---------------------------------------------------------------------------
// kernel_launch: zero -> scatter -> gemm, all on the capture stream.
// Inputs (metadata order): feature f32[50000,128], edge_src i32[800000],
// edge_dst i32[800000], W f32[128,128], b f32[128]. Output f32[50000,128].
// ---------------------------------------------------------------------------
extern "C" void kernel_launch(void* const* d_in, const int* in_sizes, int n_in,
                              void* d_out, int out_size) {
    const float* feature  = (const float*)d_in[0];
    const int*   edge_src = (const int*)d_in[1];
    const int*   edge_dst = (const int*)d_in[2];
    const float* W        = (const float*)d_in[3];
    const float* b        = (const float*)d_in[4];
    float* out = (float*)d_out;

    // 1) zero h
    {
        int n = N_NODES * D4;                 // 1.6M float4 stores
        zero_h_kernel<<<(n + 255) / 256, 256>>>();
    }
    // 2) scatter: one warp per edge
    {
        int warps = N_EDGES;
        int blocks = (warps * 32 + 255) / 256;   // 100000 blocks
        scatter_kernel<<<blocks, 256>>>(feature, edge_src, edge_dst);
    }
    // 3) gemm + bias + relu: 32 rows per block
    {
        int blocks = (N_NODES + 31) / 32;        // 1563 blocks
        gemm_bias_relu_kernel<<<blocks, 256>>>(W, b, out);
    }
}

// round 3
// speedup vs baseline: 1.2563x; 1.2563x over previous
#include <cuda_runtime.h>
#include <cstdint>

#define N_NODES 50000
#define N_EDGES 800000
#define D 128
#define D4 (D / 4)
#define SCAN_T 1024

// CSR scratch (static device globals; no allocation).
__device__ int g_deg[N_NODES];        // in-degree histogram
__device__ int g_off[N_NODES + 1];    // exclusive prefix (CSR row offsets)
__device__ int g_cursor[N_NODES];     // running fill cursor per node
__device__ int g_csr[N_EDGES];        // src node id per incoming edge, bucketed by dst

// ---------------------------------------------------------------------------
// K1: clear degree counters (must re-run every graph replay).
// ---------------------------------------------------------------------------
__global__ void clear_deg_kernel() {
    int i = blockIdx.x * blockDim.x + threadIdx.x;
    if (i < N_NODES) g_deg[i] = 0;
}

// ---------------------------------------------------------------------------
// K2: in-degree histogram. int4 loads, 4 int atomics per thread.
// 800k int REDs over 50k addresses (avg 16/addr) — cheap.
// ---------------------------------------------------------------------------
__global__ void hist_kernel(const int* __restrict__ edge_dst) {
    int i = blockIdx.x * blockDim.x + threadIdx.x;
    if (i < N_EDGES / 4) {
        int4 d = reinterpret_cast<const int4*>(edge_dst)[i];
        atomicAdd(&g_deg[d.x], 1);
        atomicAdd(&g_deg[d.y], 1);
        atomicAdd(&g_deg[d.z], 1);
        atomicAdd(&g_deg[d.w], 1);
    }
}

// ---------------------------------------------------------------------------
// K3: single-block exclusive scan over 50k degrees -> g_off, g_cursor.
// Each thread sums a 49-element chunk; Hillis-Steele over 1024 partials.
// ---------------------------------------------------------------------------
__global__ void scan_kernel() {
    __shared__ int s_part[SCAN_T];
    int t = threadIdx.x;
    const int C = (N_NODES + SCAN_T - 1) / SCAN_T;   // 49
    int start = t * C;
    int end = start + C; if (end > N_NODES) end = N_NODES;

    int sum = 0;
    for (int i = start; i < end; i++) sum += g_deg[i];
    s_part[t] = sum;
    __syncthreads();

    for (int d = 1; d < SCAN_T; d <<= 1) {
        int v = 0;
        if (t >= d) v = s_part[t - d];
        __syncthreads();
        if (t >= d) s_part[t] += v;
        __syncthreads();
    }

    int run = (t == 0) ? 0 : s_part[t - 1];
    for (int i = start; i < end; i++) {
        g_off[i] = run;
        g_cursor[i] = run;
        run += g_deg[i];
    }
    if (t == SCAN_T - 1) g_off[N_NODES] = s_part[SCAN_T - 1];
}

// ---------------------------------------------------------------------------
// K4: bucket fill — scatter each edge's src id into its dst's CSR segment.
// 800k int atomics-with-return + 800k scattered 4B stores.
// ---------------------------------------------------------------------------
__global__ void bucket_kernel(const int* __restrict__ edge_src,
                              const int* __restrict__ edge_dst) {
    int i = blockIdx.x * blockDim.x + threadIdx.x;
    if (i < N_EDGES / 4) {
        int4 d = reinterpret_cast<const int4*>(edge_dst)[i];
        int4 s = reinterpret_cast<const int4*>(edge_src)[i];
        g_csr[atomicAdd(&g_cursor[d.x], 1)] = s.x;
        g_csr[atomicAdd(&g_cursor[d.y], 1)] = s.y;
        g_csr[atomicAdd(&g_cursor[d.z], 1)] = s.z;
        g_csr[atomicAdd(&g_cursor[d.w], 1)] = s.w;
    }
}

// ---------------------------------------------------------------------------
// K5: fused aggregate + GEMM + bias + relu.
// 8 warps/block; each warp owns 4 nodes. Phase 1: gather-sum the node's
// incoming feature rows into registers (pure L2 reads, no atomics), stage to
// smem. Phase 2: 4-row x 128-col GEMM with packed fma.rn.f32x2, W L1-hot.
// ---------------------------------------------------------------------------
__global__ void agg_gemm_kernel(const float* __restrict__ feature,
                                const float* __restrict__ W,
                                const float* __restrict__ b,
                                float* __restrict__ out) {
    __shared__ float s_h[8][4][D];   // 16 KB

    int warp = threadIdx.x >> 5;
    int lane = threadIdx.x & 31;
    int row0 = (blockIdx.x * 8 + warp) * 4;

    const float4* f4 = reinterpret_cast<const float4*>(feature);

    // Phase 1: per-node gather-accumulate.
    #pragma unroll
    for (int r = 0; r < 4; r++) {
        int node = row0 + r;
        float4 acc = make_float4(0.f, 0.f, 0.f, 0.f);
        if (node < N_NODES) {
            int j  = g_off[node];
            int j1 = g_off[node + 1];
            // 2-wide unroll for MLP; tails handled below.
            for (; j + 2 <= j1; j += 2) {
                int s0 = g_csr[j];
                int s1 = g_csr[j + 1];
                float4 v0 = __ldg(f4 + (size_t)s0 * D4 + lane);
                float4 v1 = __ldg(f4 + (size_t)s1 * D4 + lane);
                acc.x += v0.x; acc.y += v0.y; acc.z += v0.z; acc.w += v0.w;
                acc.x += v1.x; acc.y += v1.y; acc.z += v1.z; acc.w += v1.w;
            }
            if (j < j1) {
                int s0 = g_csr[j];
                float4 v0 = __ldg(f4 + (size_t)s0 * D4 + lane);
                acc.x += v0.x; acc.y += v0.y; acc.z += v0.z; acc.w += v0.w;
            }
        }
        reinterpret_cast<float4*>(&s_h[warp][r][0])[lane] = acc;
    }
    __syncwarp();

    // Phase 2: out[row, :] = relu(h_row @ W + b), 4 rows per warp.
    unsigned long long acc[4][2];
    #pragma unroll
    for (int r = 0; r < 4; r++) { acc[r][0] = 0ull; acc[r][1] = 0ull; }

    const float4* W4 = reinterpret_cast<const float4*>(W);
    #pragma unroll 4
    for (int k = 0; k < D; k++) {
        float4 wv = __ldg(W4 + (size_t)k * D4 + lane);
        unsigned long long w01, w23;
        asm("mov.b64 %0, {%1, %2};" : "=l"(w01) : "f"(wv.x), "f"(wv.y));
        asm("mov.b64 %0, {%1, %2};" : "=l"(w23) : "f"(wv.z), "f"(wv.w));
        #pragma unroll
        for (int r = 0; r < 4; r++) {
            float hv = s_h[warp][r][k];
            unsigned long long hh;
            asm("mov.b64 %0, {%1, %1};" : "=l"(hh) : "f"(hv));
            asm("fma.rn.f32x2 %0, %1, %2, %0;" : "+l"(acc[r][0]) : "l"(hh), "l"(w01));
            asm("fma.rn.f32x2 %0, %1, %2, %0;" : "+l"(acc[r][1]) : "l"(hh), "l"(w23));
        }
    }

    float4 bv = __ldg(reinterpret_cast<const float4*>(b) + lane);
    #pragma unroll
    for (int r = 0; r < 4; r++) {
        int row = row0 + r;
        if (row >= N_NODES) break;
        float a0, a1, a2, a3;
        asm("mov.b64 {%0, %1}, %2;" : "=f"(a0), "=f"(a1) : "l"(acc[r][0]));
        asm("mov.b64 {%0, %1}, %2;" : "=f"(a2), "=f"(a3) : "l"(acc[r][1]));
        float4 o;
        o.x = fmaxf(a0 + bv.x, 0.f);
        o.y = fmaxf(a1 + bv.y, 0.f);
        o.z = fmaxf(a2 + bv.z, 0.f);
        o.w = fmaxf(a3 + bv.w, 0.f);
        reinterpret_cast<float4*>(out)[(size_t)row * D4 + lane] = o;
    }
}

// ---------------------------------------------------------------------------
// Inputs (metadata order): feature f32[50000,128], edge_src i32[800000],
// edge_dst i32[800000], W f32[128,128], b f32[128]. Output f32[50000,128].
// ---------------------------------------------------------------------------
extern "C" void kernel_launch(void* const* d_in, const int* in_sizes, int n_in,
                              void* d_out, int out_size) {
    const float* feature  = (const float*)d_in[0];
    const int*   edge_src = (const int*)d_in[1];
    const int*   edge_dst = (const int*)d_in[2];
    const float* W        = (const float*)d_in[3];
    const float* b        = (const float*)d_in[4];
    float* out = (float*)d_out;

    clear_deg_kernel<<<(N_NODES + 255) / 256, 256>>>();
    hist_kernel<<<(N_EDGES / 4 + 255) / 256, 256>>>(edge_dst);
    scan_kernel<<<1, SCAN_T>>>();
    bucket_kernel<<<(N_EDGES / 4 + 255) / 256, 256>>>(edge_src, edge_dst);
    agg_gemm_kernel<<<(N_NODES + 31) / 32, 256>>>(feature, W, b, out);
}